// round 14
// baseline (speedup 1.0000x reference)
#include <cuda_runtime.h>
#include <cuda_fp16.h>
#include <cstdint>

#define E_DIM 1024
#define HEADS 16
#define HD 64
#define BATCH 4
#define SEQ 2048
#define BS (BATCH*SEQ)   // 8192

#define QSCALE 0.18033688011112042f   // 0.125 * log2(e)

// ---------------- scratch (device globals: allocation-guard safe) ----------
__device__ __align__(16) __half g_qh[BATCH*HEADS*SEQ*HD];
__device__ __align__(16) __half g_kh[BATCH*HEADS*SEQ*HD];
__device__ __align__(16) __half g_vh[BATCH*HEADS*SEQ*HD];

__device__ __align__(16) __half g_xh[BS*E_DIM];
__device__ __align__(16) __half g_yh[BS*E_DIM];
__device__ __align__(16) __half g_wah[3*E_DIM*E_DIM];
__device__ __align__(16) __half g_wph[E_DIM*E_DIM];

// ---------------- PTX helpers ------------------------------------------------
__device__ __forceinline__ uint32_t smem_u32(const void* p) {
    uint32_t a;
    asm("{ .reg .u64 t; cvta.to.shared.u64 t, %1; cvt.u32.u64 %0, t; }"
        : "=r"(a) : "l"(p));
    return a;
}
#define CP_ASYNC16(sa, ga) \
    asm volatile("cp.async.cg.shared.global [%0], [%1], 16;" :: "r"(sa), "l"(ga))
#define CP_COMMIT() asm volatile("cp.async.commit_group;" ::: "memory")
#define CP_WAIT0()  asm volatile("cp.async.wait_group 0;" ::: "memory")
#define CP_WAIT1()  asm volatile("cp.async.wait_group 1;" ::: "memory")

__device__ __forceinline__ void ldsm_x4(uint32_t& r0, uint32_t& r1,
                                        uint32_t& r2, uint32_t& r3, uint32_t addr) {
    asm volatile("ldmatrix.sync.aligned.m8n8.x4.shared.b16 {%0,%1,%2,%3}, [%4];"
                 : "=r"(r0), "=r"(r1), "=r"(r2), "=r"(r3) : "r"(addr));
}
__device__ __forceinline__ void ldsm_x4t(uint32_t& r0, uint32_t& r1,
                                         uint32_t& r2, uint32_t& r3, uint32_t addr) {
    asm volatile("ldmatrix.sync.aligned.m8n8.x4.trans.shared.b16 {%0,%1,%2,%3}, [%4];"
                 : "=r"(r0), "=r"(r1), "=r"(r2), "=r"(r3) : "r"(addr));
}
__device__ __forceinline__ void mma16816(float* d, const uint32_t* a, const uint32_t* b) {
    asm volatile(
        "mma.sync.aligned.m16n8k16.row.col.f32.f16.f16.f32 "
        "{%0,%1,%2,%3}, {%4,%5,%6,%7}, {%8,%9}, {%0,%1,%2,%3};"
        : "+f"(d[0]), "+f"(d[1]), "+f"(d[2]), "+f"(d[3])
        : "r"(a[0]), "r"(a[1]), "r"(a[2]), "r"(a[3]), "r"(b[0]), "r"(b[1]));
}
__device__ __forceinline__ void mma2(float* d, const uint32_t* a, uint32_t b0, uint32_t b1) {
    asm volatile(
        "mma.sync.aligned.m16n8k16.row.col.f32.f16.f16.f32 "
        "{%0,%1,%2,%3}, {%4,%5,%6,%7}, {%8,%9}, {%0,%1,%2,%3};"
        : "+f"(d[0]), "+f"(d[1]), "+f"(d[2]), "+f"(d[3])
        : "r"(a[0]), "r"(a[1]), "r"(a[2]), "r"(a[3]), "r"(b0), "r"(b1));
}

// ---------------- prep kernels ---------------------------------------------
__global__ __launch_bounds__(256)
void cast_f16(const float* __restrict__ src, __half* __restrict__ dst)
{
    int i = (blockIdx.x * 256 + threadIdx.x) * 4;
    float4 v = *(const float4*)(src + i);
    *(__half2*)(dst + i)     = __floats2half2_rn(v.x, v.y);
    *(__half2*)(dst + i + 2) = __floats2half2_rn(v.z, v.w);
}

__global__ __launch_bounds__(256)
void wcast_t(const float* __restrict__ W, __half* __restrict__ Wh, int N)
{
    __shared__ float tile[32][33];
    int c0 = blockIdx.x * 32;
    int r0 = blockIdx.y * 32;
    int tx = threadIdx.x & 31, ty = threadIdx.x >> 5;
    #pragma unroll
    for (int i = ty; i < 32; i += 8)
        tile[i][tx] = W[(size_t)(r0 + i) * N + c0 + tx];
    __syncthreads();
    #pragma unroll
    for (int i = ty; i < 32; i += 8)
        Wh[(size_t)(c0 + i) * 1024 + r0 + tx] = __float2half_rn(tile[tx][i]);
}

// ---------------- HMMA GEMM (CTA 128x256, warp 64x64, 1 CTA/SM) -------------
// fp16 1-product, K-chunk 64, double-buffered.
// Buffer: A(16K) + B(32K) = 48K; x2 = 96K smem.
// MODE 0: -> q(QSCALE)/k/v fp16 [B,H,S,D];  MODE 1: -> out fp32
#define GEMM_BUFB 49152u
#define GEMM_BOFF 16384u
#define GEMM_SMEM (2*49152)   // 98304

template<int MODE>
__global__ __launch_bounds__(256, 1)
void gemm_mma(const __half* __restrict__ Ah, const __half* __restrict__ Bh,
              const float* __restrict__ bias, float* __restrict__ out)
{
    extern __shared__ char smem[];
    const uint32_t sb = smem_u32(smem);
    const int tid  = threadIdx.x;
    const int wid  = tid >> 5;
    const int lane = tid & 31;
    const int m0 = blockIdx.y * 128;
    const int n0 = blockIdx.x * 256;

    const int wm = wid & 1;      // 0..1  (64 rows)
    const int wn = wid >> 1;     // 0..3  (64 cols)
    const int lr = lane & 7;
    const int lg = lane >> 3;

    float acc[4][8][4];
    #pragma unroll
    for (int i = 0; i < 4; i++)
        #pragma unroll
        for (int j = 0; j < 8; j++)
            #pragma unroll
            for (int r = 0; r < 4; r++) acc[i][j][r] = 0.0f;

    auto load_chunk = [&](int c) {
        const int k0 = c * 64;
        const uint32_t sbase = sb + (uint32_t)(c & 1) * GEMM_BUFB;
        #pragma unroll
        for (int t = 0; t < 4; t++) {          // A: 128 rows
            int u = tid + t * 256;
            int r = u >> 3, seg = u & 7;
            uint32_t soff = (uint32_t)(r * 128 + ((seg ^ (r & 7)) << 4));
            CP_ASYNC16(sbase + soff, Ah + (size_t)(m0 + r) * 1024 + k0 + seg * 8);
        }
        #pragma unroll
        for (int t = 0; t < 8; t++) {          // B: 256 rows
            int u = tid + t * 256;
            int r = u >> 3, seg = u & 7;
            uint32_t soff = (uint32_t)(r * 128 + ((seg ^ (r & 7)) << 4));
            CP_ASYNC16(sbase + GEMM_BOFF + soff,
                       Bh + (size_t)(n0 + r) * 1024 + k0 + seg * 8);
        }
        CP_COMMIT();
    };

    load_chunk(0);

    for (int c = 0; c < 16; c++) {
        CP_WAIT0();
        __syncthreads();
        if (c + 1 < 16) load_chunk(c + 1);

        const uint32_t sbase = sb + (uint32_t)(c & 1) * GEMM_BUFB;
        #pragma unroll
        for (int s = 0; s < 4; s++) {
            uint32_t ah[4][4], bh[8][2];
            #pragma unroll
            for (int i = 0; i < 4; i++) {
                int row = wm * 64 + i * 16 + lr + (lg & 1) * 8;
                int seg = 2 * s + (lg >> 1);
                uint32_t ad = sbase + (uint32_t)(row * 128 +
                              ((seg ^ (row & 7)) << 4));
                ldsm_x4(ah[i][0], ah[i][1], ah[i][2], ah[i][3], ad);
            }
            #pragma unroll
            for (int p = 0; p < 4; p++) {
                int row = wn * 64 + p * 16 + lr + (lg >> 1) * 8;
                int seg = 2 * s + (lg & 1);
                uint32_t bd = sbase + GEMM_BOFF + (uint32_t)(row * 128 +
                              ((seg ^ (row & 7)) << 4));
                uint32_t r0, r1, r2, r3;
                ldsm_x4(r0, r1, r2, r3, bd);
                bh[2*p][0] = r0; bh[2*p][1] = r1;
                bh[2*p+1][0] = r2; bh[2*p+1][1] = r3;
            }
            #pragma unroll
            for (int i = 0; i < 4; i++)
                #pragma unroll
                for (int j = 0; j < 8; j++)
                    mma16816(acc[i][j], ah[i], bh[j]);
        }
    }

    const int mrow = m0 + wm * 64 + (lane >> 2);
    const int ncol = n0 + wn * 64 + (lane & 3) * 2;
    #pragma unroll
    for (int i = 0; i < 4; i++) {
        #pragma unroll
        for (int j = 0; j < 8; j++) {
            int m = mrow + i * 16;
            int n = ncol + j * 8;
            float b0 = __ldg(&bias[n]), b1 = __ldg(&bias[n + 1]);
            float f0 = acc[i][j][0] + b0, f1 = acc[i][j][1] + b1;
            float f2 = acc[i][j][2] + b0, f3 = acc[i][j][3] + b1;
            if (MODE == 0) {
                int sec = n >> 10;
                int e   = n & 1023;
                int hh  = e >> 6;
                int d   = e & 63;
                int b_ = m >> 11, s_ = m & 2047;
                size_t o0 = ((size_t)((b_ * HEADS + hh) * SEQ) + s_) * HD + d;
                size_t o1 = o0 + 8 * HD;
                __half* dst;
                if (sec == 0) {
                    dst = g_qh;
                    f0 *= QSCALE; f1 *= QSCALE; f2 *= QSCALE; f3 *= QSCALE;
                } else {
                    dst = (sec == 1) ? g_kh : g_vh;
                }
                *(__half2*)(dst + o0) = __floats2half2_rn(f0, f1);
                *(__half2*)(dst + o1) = __floats2half2_rn(f2, f3);
            } else {
                *(float2*)(out + (size_t)m * 1024 + n) = {f0, f1};
                *(float2*)(out + (size_t)(m + 8) * 1024 + n) = {f2, f3};
            }
        }
    }
}

// ---------------- HMMA flash attention (1-product fp16, 3-stage KV) ---------
#define ATT_SMEM (16384 + 3*16384)   // 65536

__global__ __launch_bounds__(256, 2)
void flash_attn_mma()
{
    extern __shared__ char smc[];
    const uint32_t sb = smem_u32(smc);
    const int tid  = threadIdx.x;
    const int wid  = tid >> 5;
    const int lane = tid & 31;
    const int lr = lane & 7;
    const int lg = lane >> 3;
    const int g  = lane >> 2;
    const int t2 = (lane & 3) * 2;

    const int qi = (int)gridDim.x - 1 - (int)blockIdx.x;
    const int qb = qi * 128;
    const int hh = blockIdx.y;
    const int bb = blockIdx.z;
    const size_t bhof = ((size_t)(bb * HEADS + hh)) * SEQ * HD;

    const __half* qh_g = g_qh + bhof;
    const __half* kh_g = g_kh + bhof;
    const __half* vh_g = g_vh + bhof;

    const uint32_t QH = sb;
    const uint32_t BUF0 = sb + 16384;

    #pragma unroll
    for (int u = tid; u < 1024; u += 256) {
        int row = u >> 3, seg = u & 7;
        uint32_t so = (uint32_t)(row * 128 + ((seg ^ (row & 7)) << 4));
        size_t go = (size_t)(qb + row) * 64 + seg * 8;
        CP_ASYNC16(QH + so, qh_g + go);
    }

    auto load_kv = [&](int kj, int buf) {
        uint32_t base = BUF0 + (uint32_t)buf * 16384u;
        #pragma unroll
        for (int u = tid; u < 512; u += 256) {
            int row = u >> 3, seg = u & 7;
            uint32_t so = (uint32_t)(row * 128 + ((seg ^ (row & 7)) << 4));
            size_t go = (size_t)(kj * 64 + row) * 64 + seg * 8;
            CP_ASYNC16(base + so,         kh_g + go);
            CP_ASYNC16(base + 8192 + so,  vh_g + go);
        }
        CP_COMMIT();
    };

    const int nkj = 2 * qi + 2;
    load_kv(0, 0);
    if (nkj > 1) load_kv(1, 1);

    uint32_t qfh[4][4];
    float y[8][4];
    #pragma unroll
    for (int j = 0; j < 8; j++)
        #pragma unroll
        for (int r = 0; r < 4; r++) y[j][r] = 0.0f;
    float m0 = -1e30f, m1 = -1e30f, l0 = 0.0f, l1 = 0.0f;
    bool qloaded = false;

    const int wr0 = qb + wid * 16;

    int buf = 0;
    for (int kj = 0; kj < nkj; kj++) {
        if (kj + 1 < nkj) CP_WAIT1(); else CP_WAIT0();
        __syncthreads();
        if (kj + 2 < nkj) {
            int nb = buf - 1; if (nb < 0) nb += 3;
            load_kv(kj + 2, nb);
        }

        if (!qloaded) {
            qloaded = true;
            #pragma unroll
            for (int kc = 0; kc < 4; kc++) {
                int row = wid * 16 + lr + (lg & 1) * 8;
                int seg = 2 * kc + (lg >> 1);
                uint32_t so = (uint32_t)(row * 128 + ((seg ^ (row & 7)) << 4));
                ldsm_x4(qfh[kc][0], qfh[kc][1], qfh[kc][2], qfh[kc][3], QH + so);
            }
        }

        const int c0t = kj * 64;
        const uint32_t B = BUF0 + (uint32_t)buf * 16384u;
        if (++buf == 3) buf = 0;
        if (c0t > wr0 + 15) continue;

        float s[8][4];
        #pragma unroll
        for (int j = 0; j < 8; j++)
            #pragma unroll
            for (int r = 0; r < 4; r++) s[j][r] = 0.0f;

        #pragma unroll
        for (int kc = 0; kc < 4; kc++) {
            uint32_t kh[4][4];
            #pragma unroll
            for (int p = 0; p < 4; p++) {
                int row = p * 16 + lr + (lg >> 1) * 8;
                int seg = 2 * kc + (lg & 1);
                uint32_t so = (uint32_t)(row * 128 + ((seg ^ (row & 7)) << 4));
                ldsm_x4(kh[p][0], kh[p][1], kh[p][2], kh[p][3], B + so);
            }
            #pragma unroll
            for (int p = 0; p < 4; p++) {
                mma2(s[2*p],   qfh[kc], kh[p][0], kh[p][1]);
                mma2(s[2*p+1], qfh[kc], kh[p][2], kh[p][3]);
            }
        }

        if (c0t + 63 > wr0) {
            int R0 = wr0 + g, R1 = wr0 + g + 8;
            #pragma unroll
            for (int j = 0; j < 8; j++) {
                int cg = c0t + j * 8 + t2;
                if (cg     > R0) s[j][0] = -1e30f;
                if (cg + 1 > R0) s[j][1] = -1e30f;
                if (cg     > R1) s[j][2] = -1e30f;
                if (cg + 1 > R1) s[j][3] = -1e30f;
            }
        }

        float mx0 = -1e30f, mx1 = -1e30f;
        #pragma unroll
        for (int j = 0; j < 8; j++) {
            mx0 = fmaxf(mx0, fmaxf(s[j][0], s[j][1]));
            mx1 = fmaxf(mx1, fmaxf(s[j][2], s[j][3]));
        }
        mx0 = fmaxf(mx0, __shfl_xor_sync(0xffffffffu, mx0, 1));
        mx0 = fmaxf(mx0, __shfl_xor_sync(0xffffffffu, mx0, 2));
        mx1 = fmaxf(mx1, __shfl_xor_sync(0xffffffffu, mx1, 1));
        mx1 = fmaxf(mx1, __shfl_xor_sync(0xffffffffu, mx1, 2));
        float mn0 = fmaxf(m0, mx0), mn1 = fmaxf(m1, mx1);
        float a0 = exp2f(m0 - mn0), a1 = exp2f(m1 - mn1);
        m0 = mn0; m1 = mn1;

        float s0 = 0.0f, s1 = 0.0f;
        uint32_t ph[4][4];
        #pragma unroll
        for (int j = 0; j < 8; j++) {
            float p00 = exp2f(s[j][0] - mn0);
            float p01 = exp2f(s[j][1] - mn0);
            float p10 = exp2f(s[j][2] - mn1);
            float p11 = exp2f(s[j][3] - mn1);
            s0 += p00 + p01;
            s1 += p10 + p11;
            uint32_t hA, hB;
            { __half2 v = __floats2half2_rn(p00, p01); hA = *(uint32_t*)&v; }
            { __half2 v = __floats2half2_rn(p10, p11); hB = *(uint32_t*)&v; }
            int kc = j >> 1;
            if ((j & 1) == 0) { ph[kc][0] = hA; ph[kc][1] = hB; }
            else              { ph[kc][2] = hA; ph[kc][3] = hB; }
        }
        s0 += __shfl_xor_sync(0xffffffffu, s0, 1);
        s0 += __shfl_xor_sync(0xffffffffu, s0, 2);
        s1 += __shfl_xor_sync(0xffffffffu, s1, 1);
        s1 += __shfl_xor_sync(0xffffffffu, s1, 2);
        l0 = l0 * a0 + s0;
        l1 = l1 * a1 + s1;
        #pragma unroll
        for (int j = 0; j < 8; j++) {
            y[j][0] *= a0; y[j][1] *= a0;
            y[j][2] *= a1; y[j][3] *= a1;
        }

        #pragma unroll
        for (int kc = 0; kc < 4; kc++) {
            uint32_t vh[4][4];
            #pragma unroll
            for (int dg = 0; dg < 4; dg++) {
                int row = kc * 16 + (lg & 1) * 8 + lr;
                int seg = 2 * dg + (lg >> 1);
                uint32_t so = (uint32_t)(row * 128 + ((seg ^ (row & 7)) << 4));
                ldsm_x4t(vh[dg][0], vh[dg][1], vh[dg][2], vh[dg][3], B + 8192 + so);
            }
            #pragma unroll
            for (int dg = 0; dg < 4; dg++) {
                mma2(y[2*dg],   ph[kc], vh[dg][0], vh[dg][1]);
                mma2(y[2*dg+1], ph[kc], vh[dg][2], vh[dg][3]);
            }
        }
    }

    const float i0 = 1.0f / l0, i1 = 1.0f / l1;
    const int r0 = wr0 + g;
    const int r1 = r0 + 8;
    const size_t rb0 = ((size_t)(bb * SEQ + r0)) * E_DIM + hh * HD;
    const size_t rb1 = ((size_t)(bb * SEQ + r1)) * E_DIM + hh * HD;
    #pragma unroll
    for (int j = 0; j < 8; j++) {
        int col = j * 8 + t2;
        *(__half2*)(g_yh + rb0 + col) =
            __floats2half2_rn(y[j][0] * i0, y[j][1] * i0);
        *(__half2*)(g_yh + rb1 + col) =
            __floats2half2_rn(y[j][2] * i1, y[j][3] * i1);
    }
}

// ---------------------------------------------------------------------------
extern "C" void kernel_launch(void* const* d_in, const int* in_sizes, int n_in,
                              void* d_out, int out_size)
{
    const float* x      = (const float*)d_in[0];
    const float* W_attn = (const float*)d_in[1];
    const float* b_attn = (const float*)d_in[2];
    const float* W_proj = (const float*)d_in[3];
    const float* b_proj = (const float*)d_in[4];
    float* out = (float*)d_out;

    cudaFuncSetAttribute(flash_attn_mma,
                         cudaFuncAttributeMaxDynamicSharedMemorySize, ATT_SMEM);
    cudaFuncSetAttribute(gemm_mma<0>,
                         cudaFuncAttributeMaxDynamicSharedMemorySize, GEMM_SMEM);
    cudaFuncSetAttribute(gemm_mma<1>,
                         cudaFuncAttributeMaxDynamicSharedMemorySize, GEMM_SMEM);

    __half *xh, *yh, *wah, *wph;
    cudaGetSymbolAddress((void**)&xh,  g_xh);
    cudaGetSymbolAddress((void**)&yh,  g_yh);
    cudaGetSymbolAddress((void**)&wah, g_wah);
    cudaGetSymbolAddress((void**)&wph, g_wph);

    cast_f16<<<BS * E_DIM / 1024, 256>>>(x, xh);
    {
        dim3 g(3 * E_DIM / 32, E_DIM / 32);
        wcast_t<<<g, 256>>>(W_attn, wah, 3 * E_DIM);
    }
    {
        dim3 g(E_DIM / 32, E_DIM / 32);
        wcast_t<<<g, 256>>>(W_proj, wph, E_DIM);
    }

    // 1) QKV GEMM (128x256 tile) -> q(QSCALE)/k/v fp16 [B,H,S,D]
    {
        dim3 grid(3 * E_DIM / 256, BS / 128);   // 12 x 64
        gemm_mma<0><<<grid, 256, GEMM_SMEM>>>(xh, wah, b_attn, nullptr);
    }

    // 2) causal flash attention -> yh fp16
    {
        dim3 grid(SEQ / 128, HEADS, BATCH);
        flash_attn_mma<<<grid, 256, ATT_SMEM>>>();
    }

    // 3) proj GEMM (128x256 tile) -> out
    {
        dim3 grid(E_DIM / 256, BS / 128);       // 4 x 64
        gemm_mma<1><<<grid, 256, GEMM_SMEM>>>(yh, wph, b_proj, out);
    }
}

// round 15
// speedup vs baseline: 1.0799x; 1.0799x over previous
#include <cuda_runtime.h>
#include <cuda_fp16.h>
#include <cstdint>

#define E_DIM 1024
#define HEADS 16
#define HD 64
#define BATCH 4
#define SEQ 2048
#define BS (BATCH*SEQ)   // 8192

#define QSCALE 0.18033688011112042f   // 0.125 * log2(e)

// ---------------- scratch (device globals: allocation-guard safe) ----------
__device__ __align__(16) __half g_qh[BATCH*HEADS*SEQ*HD];
__device__ __align__(16) __half g_kh[BATCH*HEADS*SEQ*HD];
__device__ __align__(16) __half g_vh[BATCH*HEADS*SEQ*HD];

__device__ __align__(16) __half g_xh[BS*E_DIM];
__device__ __align__(16) __half g_yh[BS*E_DIM];
__device__ __align__(16) __half g_wah[3*E_DIM*E_DIM];
__device__ __align__(16) __half g_wph[E_DIM*E_DIM];

// ---------------- PTX helpers ------------------------------------------------
__device__ __forceinline__ uint32_t smem_u32(const void* p) {
    uint32_t a;
    asm("{ .reg .u64 t; cvta.to.shared.u64 t, %1; cvt.u32.u64 %0, t; }"
        : "=r"(a) : "l"(p));
    return a;
}
#define CP_ASYNC16(sa, ga) \
    asm volatile("cp.async.cg.shared.global [%0], [%1], 16;" :: "r"(sa), "l"(ga))
#define CP_COMMIT() asm volatile("cp.async.commit_group;" ::: "memory")
#define CP_WAIT0()  asm volatile("cp.async.wait_group 0;" ::: "memory")

__device__ __forceinline__ void ldsm_x4(uint32_t& r0, uint32_t& r1,
                                        uint32_t& r2, uint32_t& r3, uint32_t addr) {
    asm volatile("ldmatrix.sync.aligned.m8n8.x4.shared.b16 {%0,%1,%2,%3}, [%4];"
                 : "=r"(r0), "=r"(r1), "=r"(r2), "=r"(r3) : "r"(addr));
}
__device__ __forceinline__ void ldsm_x4t(uint32_t& r0, uint32_t& r1,
                                         uint32_t& r2, uint32_t& r3, uint32_t addr) {
    asm volatile("ldmatrix.sync.aligned.m8n8.x4.trans.shared.b16 {%0,%1,%2,%3}, [%4];"
                 : "=r"(r0), "=r"(r1), "=r"(r2), "=r"(r3) : "r"(addr));
}
__device__ __forceinline__ void mma16816(float* d, const uint32_t* a, const uint32_t* b) {
    asm volatile(
        "mma.sync.aligned.m16n8k16.row.col.f32.f16.f16.f32 "
        "{%0,%1,%2,%3}, {%4,%5,%6,%7}, {%8,%9}, {%0,%1,%2,%3};"
        : "+f"(d[0]), "+f"(d[1]), "+f"(d[2]), "+f"(d[3])
        : "r"(a[0]), "r"(a[1]), "r"(a[2]), "r"(a[3]), "r"(b[0]), "r"(b[1]));
}
__device__ __forceinline__ void mma2(float* d, const uint32_t* a, uint32_t b0, uint32_t b1) {
    asm volatile(
        "mma.sync.aligned.m16n8k16.row.col.f32.f16.f16.f32 "
        "{%0,%1,%2,%3}, {%4,%5,%6,%7}, {%8,%9}, {%0,%1,%2,%3};"
        : "+f"(d[0]), "+f"(d[1]), "+f"(d[2]), "+f"(d[3])
        : "r"(a[0]), "r"(a[1]), "r"(a[2]), "r"(a[3]), "r"(b0), "r"(b1));
}

// ---------------- prep kernels ---------------------------------------------
__global__ __launch_bounds__(256)
void cast_f16(const float* __restrict__ src, __half* __restrict__ dst)
{
    int i = (blockIdx.x * 256 + threadIdx.x) * 4;
    float4 v = *(const float4*)(src + i);
    *(__half2*)(dst + i)     = __floats2half2_rn(v.x, v.y);
    *(__half2*)(dst + i + 2) = __floats2half2_rn(v.z, v.w);
}

__global__ __launch_bounds__(256)
void wcast_t(const float* __restrict__ W, __half* __restrict__ Wh, int N)
{
    __shared__ float tile[32][33];
    int c0 = blockIdx.x * 32;
    int r0 = blockIdx.y * 32;
    int tx = threadIdx.x & 31, ty = threadIdx.x >> 5;
    #pragma unroll
    for (int i = ty; i < 32; i += 8)
        tile[i][tx] = W[(size_t)(r0 + i) * N + c0 + tx];
    __syncthreads();
    #pragma unroll
    for (int i = ty; i < 32; i += 8)
        Wh[(size_t)(c0 + i) * 1024 + r0 + tx] = __float2half_rn(tile[tx][i]);
}

// ---------------- HMMA GEMM (R12 config: 128x128, warp 64x32, K64, 2-stage) --
#define GEMM_BUFB 32768u
#define GEMM_SMEM (2*32768)

template<int MODE>
__global__ __launch_bounds__(256, 2)
void gemm_mma(const __half* __restrict__ Ah, const __half* __restrict__ Bh,
              const float* __restrict__ bias, float* __restrict__ out)
{
    extern __shared__ char smem[];
    const uint32_t sb = smem_u32(smem);
    const int tid  = threadIdx.x;
    const int wid  = tid >> 5;
    const int lane = tid & 31;
    const int m0 = blockIdx.y * 128;
    const int n0 = blockIdx.x * 128;

    const int wm = wid & 1;
    const int wn = wid >> 1;
    const int lr = lane & 7;
    const int lg = lane >> 3;

    float acc[4][4][4];
    #pragma unroll
    for (int i = 0; i < 4; i++)
        #pragma unroll
        for (int j = 0; j < 4; j++)
            #pragma unroll
            for (int r = 0; r < 4; r++) acc[i][j][r] = 0.0f;

    auto load_chunk = [&](int c) {
        const int k0 = c * 64;
        const uint32_t sbase = sb + (uint32_t)(c & 1) * GEMM_BUFB;
        #pragma unroll
        for (int t = 0; t < 4; t++) {
            int u = tid + t * 256;
            int r = u >> 3, seg = u & 7;
            uint32_t soff = (uint32_t)(r * 128 + ((seg ^ (r & 7)) << 4));
            size_t ga = (size_t)(m0 + r) * 1024 + k0 + seg * 8;
            size_t gb = (size_t)(n0 + r) * 1024 + k0 + seg * 8;
            CP_ASYNC16(sbase + soff,         Ah + ga);
            CP_ASYNC16(sbase + 16384 + soff, Bh + gb);
        }
        CP_COMMIT();
    };

    load_chunk(0);

    for (int c = 0; c < 16; c++) {
        CP_WAIT0();
        __syncthreads();
        if (c + 1 < 16) load_chunk(c + 1);

        const uint32_t sbase = sb + (uint32_t)(c & 1) * GEMM_BUFB;
        #pragma unroll
        for (int s = 0; s < 4; s++) {
            uint32_t ah[4][4], bh[4][2];
            #pragma unroll
            for (int i = 0; i < 4; i++) {
                int row = wm * 64 + i * 16 + lr + (lg & 1) * 8;
                int seg = 2 * s + (lg >> 1);
                uint32_t ad = sbase + (uint32_t)(row * 128 +
                              ((seg ^ (row & 7)) << 4));
                ldsm_x4(ah[i][0], ah[i][1], ah[i][2], ah[i][3], ad);
            }
            #pragma unroll
            for (int p = 0; p < 2; p++) {
                int row = wn * 32 + p * 16 + lr + (lg >> 1) * 8;
                int seg = 2 * s + (lg & 1);
                uint32_t bd = sbase + 16384u + (uint32_t)(row * 128 +
                              ((seg ^ (row & 7)) << 4));
                uint32_t r0, r1, r2, r3;
                ldsm_x4(r0, r1, r2, r3, bd);
                bh[2*p][0] = r0; bh[2*p][1] = r1;
                bh[2*p+1][0] = r2; bh[2*p+1][1] = r3;
            }
            #pragma unroll
            for (int i = 0; i < 4; i++)
                #pragma unroll
                for (int j = 0; j < 4; j++)
                    mma16816(acc[i][j], ah[i], bh[j]);
        }
    }

    const int mrow = m0 + wm * 64 + (lane >> 2);
    const int ncol = n0 + wn * 32 + (lane & 3) * 2;
    #pragma unroll
    for (int i = 0; i < 4; i++) {
        #pragma unroll
        for (int j = 0; j < 4; j++) {
            int m = mrow + i * 16;
            int n = ncol + j * 8;
            float b0 = __ldg(&bias[n]), b1 = __ldg(&bias[n + 1]);
            float f0 = acc[i][j][0] + b0, f1 = acc[i][j][1] + b1;
            float f2 = acc[i][j][2] + b0, f3 = acc[i][j][3] + b1;
            if (MODE == 0) {
                int sec = n >> 10;
                int e   = n & 1023;
                int hh  = e >> 6;
                int d   = e & 63;
                int b_ = m >> 11, s_ = m & 2047;
                size_t o0 = ((size_t)((b_ * HEADS + hh) * SEQ) + s_) * HD + d;
                size_t o1 = o0 + 8 * HD;
                __half* dst;
                if (sec == 0) {
                    dst = g_qh;
                    f0 *= QSCALE; f1 *= QSCALE; f2 *= QSCALE; f3 *= QSCALE;
                } else {
                    dst = (sec == 1) ? g_kh : g_vh;
                }
                *(__half2*)(dst + o0) = __floats2half2_rn(f0, f1);
                *(__half2*)(dst + o1) = __floats2half2_rn(f2, f3);
            } else {
                *(float2*)(out + (size_t)m * 1024 + n) = {f0, f1};
                *(float2*)(out + (size_t)(m + 8) * 1024 + n) = {f2, f3};
            }
        }
    }
}

// ---------------- HMMA flash attention ---------------------------------------
// 128-key chunks per barrier, processed as two 64-key halves (registers
// stay at the 64-key working set). smem: Qh(16K) + 2 x [Kh(16K) Vh(16K)] = 80K.
#define ATT_CHUNK 32768u
#define ATT_SMEM (16384 + 2*32768)   // 81920

__global__ __launch_bounds__(256, 2)
void flash_attn_mma()
{
    extern __shared__ char smc[];
    const uint32_t sb = smem_u32(smc);
    const int tid  = threadIdx.x;
    const int wid  = tid >> 5;
    const int lane = tid & 31;
    const int lr = lane & 7;
    const int lg = lane >> 3;
    const int g  = lane >> 2;
    const int t2 = (lane & 3) * 2;

    const int qi = (int)gridDim.x - 1 - (int)blockIdx.x;
    const int qb = qi * 128;
    const int hh = blockIdx.y;
    const int bb = blockIdx.z;
    const size_t bhof = ((size_t)(bb * HEADS + hh)) * SEQ * HD;

    const __half* qh_g = g_qh + bhof;
    const __half* kh_g = g_kh + bhof;
    const __half* vh_g = g_vh + bhof;

    const uint32_t QH = sb;
    const uint32_t BUF0 = sb + 16384;

    #pragma unroll
    for (int u = tid; u < 1024; u += 256) {
        int row = u >> 3, seg = u & 7;
        uint32_t so = (uint32_t)(row * 128 + ((seg ^ (row & 7)) << 4));
        size_t go = (size_t)(qb + row) * 64 + seg * 8;
        CP_ASYNC16(QH + so, qh_g + go);
    }

    // load 128-key chunk c: K rows [c*128, c*128+128) and matching V
    auto load_kv = [&](int c) {
        uint32_t base = BUF0 + (uint32_t)(c & 1) * ATT_CHUNK;
        #pragma unroll
        for (int u = tid; u < 1024; u += 256) {
            int row = u >> 3, seg = u & 7;
            uint32_t so = (uint32_t)(row * 128 + ((seg ^ (row & 7)) << 4));
            size_t go = (size_t)(c * 128 + row) * 64 + seg * 8;
            CP_ASYNC16(base + so,          kh_g + go);
            CP_ASYNC16(base + 16384 + so,  vh_g + go);
        }
        CP_COMMIT();
    };

    const int nc = qi + 1;          // 128-key chunks
    load_kv(0);

    uint32_t qfh[4][4];
    float y[8][4];
    #pragma unroll
    for (int j = 0; j < 8; j++)
        #pragma unroll
        for (int r = 0; r < 4; r++) y[j][r] = 0.0f;
    float m0 = -1e30f, m1 = -1e30f, l0 = 0.0f, l1 = 0.0f;
    bool qloaded = false;

    const int wr0 = qb + wid * 16;

    for (int c = 0; c < nc; c++) {
        CP_WAIT0();
        __syncthreads();
        if (c + 1 < nc) load_kv(c + 1);

        if (!qloaded) {
            qloaded = true;
            #pragma unroll
            for (int kc = 0; kc < 4; kc++) {
                int row = wid * 16 + lr + (lg & 1) * 8;
                int seg = 2 * kc + (lg >> 1);
                uint32_t so = (uint32_t)(row * 128 + ((seg ^ (row & 7)) << 4));
                ldsm_x4(qfh[kc][0], qfh[kc][1], qfh[kc][2], qfh[kc][3], QH + so);
            }
        }

        const uint32_t CB = BUF0 + (uint32_t)(c & 1) * ATT_CHUNK;

        #pragma unroll
        for (int half = 0; half < 2; half++) {
            const int c0t = c * 128 + half * 64;
            if (c0t > wr0 + 15) continue;

            const uint32_t BK = CB + (uint32_t)half * 8192u;
            const uint32_t BV = CB + 16384u + (uint32_t)half * 8192u;

            // ---- S = Q K^T (1-product) ----
            float s[8][4];
            #pragma unroll
            for (int j = 0; j < 8; j++)
                #pragma unroll
                for (int r = 0; r < 4; r++) s[j][r] = 0.0f;

            #pragma unroll
            for (int kc = 0; kc < 4; kc++) {
                uint32_t kh[4][4];
                #pragma unroll
                for (int p = 0; p < 4; p++) {
                    int row = p * 16 + lr + (lg >> 1) * 8;
                    int seg = 2 * kc + (lg & 1);
                    uint32_t so = (uint32_t)(row * 128 + ((seg ^ (row & 7)) << 4));
                    ldsm_x4(kh[p][0], kh[p][1], kh[p][2], kh[p][3], BK + so);
                }
                #pragma unroll
                for (int p = 0; p < 4; p++) {
                    mma2(s[2*p],   qfh[kc], kh[p][0], kh[p][1]);
                    mma2(s[2*p+1], qfh[kc], kh[p][2], kh[p][3]);
                }
            }

            // ---- causal mask ----
            if (c0t + 63 > wr0) {
                int R0 = wr0 + g, R1 = wr0 + g + 8;
                #pragma unroll
                for (int j = 0; j < 8; j++) {
                    int cg = c0t + j * 8 + t2;
                    if (cg     > R0) s[j][0] = -1e30f;
                    if (cg + 1 > R0) s[j][1] = -1e30f;
                    if (cg     > R1) s[j][2] = -1e30f;
                    if (cg + 1 > R1) s[j][3] = -1e30f;
                }
            }

            // ---- online softmax (exp2 domain) ----
            float mx0 = -1e30f, mx1 = -1e30f;
            #pragma unroll
            for (int j = 0; j < 8; j++) {
                mx0 = fmaxf(mx0, fmaxf(s[j][0], s[j][1]));
                mx1 = fmaxf(mx1, fmaxf(s[j][2], s[j][3]));
            }
            mx0 = fmaxf(mx0, __shfl_xor_sync(0xffffffffu, mx0, 1));
            mx0 = fmaxf(mx0, __shfl_xor_sync(0xffffffffu, mx0, 2));
            mx1 = fmaxf(mx1, __shfl_xor_sync(0xffffffffu, mx1, 1));
            mx1 = fmaxf(mx1, __shfl_xor_sync(0xffffffffu, mx1, 2));
            float mn0 = fmaxf(m0, mx0), mn1 = fmaxf(m1, mx1);
            float a0 = exp2f(m0 - mn0), a1 = exp2f(m1 - mn1);
            m0 = mn0; m1 = mn1;

            float s0 = 0.0f, s1 = 0.0f;
            uint32_t ph[4][4];
            #pragma unroll
            for (int j = 0; j < 8; j++) {
                float p00 = exp2f(s[j][0] - mn0);
                float p01 = exp2f(s[j][1] - mn0);
                float p10 = exp2f(s[j][2] - mn1);
                float p11 = exp2f(s[j][3] - mn1);
                s0 += p00 + p01;
                s1 += p10 + p11;
                uint32_t hA, hB;
                { __half2 v = __floats2half2_rn(p00, p01); hA = *(uint32_t*)&v; }
                { __half2 v = __floats2half2_rn(p10, p11); hB = *(uint32_t*)&v; }
                int kc = j >> 1;
                if ((j & 1) == 0) { ph[kc][0] = hA; ph[kc][1] = hB; }
                else              { ph[kc][2] = hA; ph[kc][3] = hB; }
            }
            s0 += __shfl_xor_sync(0xffffffffu, s0, 1);
            s0 += __shfl_xor_sync(0xffffffffu, s0, 2);
            s1 += __shfl_xor_sync(0xffffffffu, s1, 1);
            s1 += __shfl_xor_sync(0xffffffffu, s1, 2);
            l0 = l0 * a0 + s0;
            l1 = l1 * a1 + s1;
            #pragma unroll
            for (int j = 0; j < 8; j++) {
                y[j][0] *= a0; y[j][1] *= a0;
                y[j][2] *= a1; y[j][3] *= a1;
            }

            // ---- Y += P V (1-product) ----
            #pragma unroll
            for (int kc = 0; kc < 4; kc++) {
                uint32_t vh[4][4];
                #pragma unroll
                for (int dg = 0; dg < 4; dg++) {
                    int row = kc * 16 + (lg & 1) * 8 + lr;
                    int seg = 2 * dg + (lg >> 1);
                    uint32_t so = (uint32_t)(row * 128 + ((seg ^ (row & 7)) << 4));
                    ldsm_x4t(vh[dg][0], vh[dg][1], vh[dg][2], vh[dg][3], BV + so);
                }
                #pragma unroll
                for (int dg = 0; dg < 4; dg++) {
                    mma2(y[2*dg],   ph[kc], vh[dg][0], vh[dg][1]);
                    mma2(y[2*dg+1], ph[kc], vh[dg][2], vh[dg][3]);
                }
            }
        }
    }

    // ---- epilogue: normalize -> g_yh single fp16 [B,S,E] ----
    const float i0 = 1.0f / l0, i1 = 1.0f / l1;
    const int r0 = wr0 + g;
    const int r1 = r0 + 8;
    const size_t rb0 = ((size_t)(bb * SEQ + r0)) * E_DIM + hh * HD;
    const size_t rb1 = ((size_t)(bb * SEQ + r1)) * E_DIM + hh * HD;
    #pragma unroll
    for (int j = 0; j < 8; j++) {
        int col = j * 8 + t2;
        *(__half2*)(g_yh + rb0 + col) =
            __floats2half2_rn(y[j][0] * i0, y[j][1] * i0);
        *(__half2*)(g_yh + rb1 + col) =
            __floats2half2_rn(y[j][2] * i1, y[j][3] * i1);
    }
}

// ---------------------------------------------------------------------------
extern "C" void kernel_launch(void* const* d_in, const int* in_sizes, int n_in,
                              void* d_out, int out_size)
{
    const float* x      = (const float*)d_in[0];
    const float* W_attn = (const float*)d_in[1];
    const float* b_attn = (const float*)d_in[2];
    const float* W_proj = (const float*)d_in[3];
    const float* b_proj = (const float*)d_in[4];
    float* out = (float*)d_out;

    cudaFuncSetAttribute(flash_attn_mma,
                         cudaFuncAttributeMaxDynamicSharedMemorySize, ATT_SMEM);
    cudaFuncSetAttribute(gemm_mma<0>,
                         cudaFuncAttributeMaxDynamicSharedMemorySize, GEMM_SMEM);
    cudaFuncSetAttribute(gemm_mma<1>,
                         cudaFuncAttributeMaxDynamicSharedMemorySize, GEMM_SMEM);

    __half *xh, *yh, *wah, *wph;
    cudaGetSymbolAddress((void**)&xh,  g_xh);
    cudaGetSymbolAddress((void**)&yh,  g_yh);
    cudaGetSymbolAddress((void**)&wah, g_wah);
    cudaGetSymbolAddress((void**)&wph, g_wph);

    cast_f16<<<BS * E_DIM / 1024, 256>>>(x, xh);
    {
        dim3 g(3 * E_DIM / 32, E_DIM / 32);
        wcast_t<<<g, 256>>>(W_attn, wah, 3 * E_DIM);
    }
    {
        dim3 g(E_DIM / 32, E_DIM / 32);
        wcast_t<<<g, 256>>>(W_proj, wph, E_DIM);
    }

    // 1) QKV GEMM (R12 config) -> q(QSCALE)/k/v fp16 [B,H,S,D]
    {
        dim3 grid(3 * E_DIM / 128, BS / 128);   // 24 x 64
        gemm_mma<0><<<grid, 256, GEMM_SMEM>>>(xh, wah, b_attn, nullptr);
    }

    // 2) causal flash attention (128-key chunks) -> yh fp16
    {
        dim3 grid(SEQ / 128, HEADS, BATCH);
        flash_attn_mma<<<grid, 256, ATT_SMEM>>>();
    }

    // 3) proj GEMM -> out
    {
        dim3 grid(E_DIM / 128, BS / 128);       // 8 x 64
        gemm_mma<1><<<grid, 256, GEMM_SMEM>>>(yh, wph, b_proj, out);
    }
}